// round 10
// baseline (speedup 1.0000x reference)
#include <cuda_runtime.h>
#include <cuda_fp16.h>
#include <cstdint>
#include <cstddef>

#define SEQn 2048
#define Bn   64
#define In   256
#define Hn   256
#define G3n  768
#define TBn  32
#define NBLKn 64
#define MR   8192      // 2 dirs * 64 blocks * 64 batch
#define MI   131072    // SEQ*B

#define NT   256       // 8 warps: 2(m) x 4(n)
#define ASTH 40        // input_gemm A/B row stride (halfs)
#define A2STH 72       // phase A row stride (64+8 halfs; 144B = 16 mod 128 -> conflict-free)
#define BSTH 264       // resident-B row stride (halfs)
#define NCTA 256
#define NMP  32

// input_gemm smem (3-stage A+B pipeline, 32-wide chunks)
#define IG_BOFF_H (128 * ASTH)
#define IG_STAGE_H (IG_BOFF_H + 96 * ASTH)
#define IG_STAGE_B (IG_STAGE_H * 2)
#define IG_SMEM (3 * IG_STAGE_B)

// phase smem: 3 A stages (64-wide chunks) + resident B
#define A2_STAGE_H (128 * A2STH)                  // 9216 halfs
#define A2_STAGE_B (A2_STAGE_H * 2)               // 18432 B
#define PP_B_OFF_H (3 * A2_STAGE_H)
#define PP_SMEM ((PP_B_OFF_H + 96 * BSTH) * 2)    // 105984 B

__device__ __half g_GX[(size_t)2 * MI * G3n];
__device__ __half g_X16[(size_t)MI * In];
__device__ __half g_Wih16[(size_t)2 * G3n * In];
__device__ __half g_Whh16[(size_t)2 * G3n * Hn];
__device__ __half g_State16[2][(size_t)MR * Hn];
__device__ __half g_End16[(size_t)MR * Hn];
__device__ unsigned g_barc;
__device__ unsigned g_barg;
__device__ unsigned g_lbc[NMP];
__device__ unsigned g_lbg[NMP];

static __device__ __forceinline__ void mma16(float c[4], const uint32_t a[4],
                                             uint32_t b0, uint32_t b1) {
    asm volatile(
        "mma.sync.aligned.m16n8k16.row.col.f32.f16.f16.f32 "
        "{%0,%1,%2,%3}, {%4,%5,%6,%7}, {%8,%9}, {%0,%1,%2,%3};\n"
        : "+f"(c[0]), "+f"(c[1]), "+f"(c[2]), "+f"(c[3])
        : "r"(a[0]), "r"(a[1]), "r"(a[2]), "r"(a[3]), "r"(b0), "r"(b1));
}

#define LDSM4(r, addr) \
    asm volatile("ldmatrix.sync.aligned.m8n8.x4.shared.b16 {%0,%1,%2,%3}, [%4];" \
                 : "=r"((r)[0]), "=r"((r)[1]), "=r"((r)[2]), "=r"((r)[3]) : "r"(addr))

static __device__ __forceinline__ void cpasync16(uint32_t dst, const void* src, int srcsize) {
    asm volatile("cp.async.cg.shared.global [%0], [%1], 16, %2;\n"
                 :: "r"(dst), "l"(src), "r"(srcsize));
}
#define CP_COMMIT() asm volatile("cp.async.commit_group;\n" ::: "memory")
#define CP_WAIT1()  asm volatile("cp.async.wait_group 1;\n" ::: "memory")

// ---------------------------------------------------------------------------
#define NX4 ((size_t)MI * In / 4)
#define NW4 ((size_t)G3n * In / 4)

__global__ void convert_all(const float* __restrict__ X,
                            const float* __restrict__ Wih_f, const float* __restrict__ Wih_b,
                            const float* __restrict__ Whh_f, const float* __restrict__ Whh_b)
{
    size_t i = (size_t)blockIdx.x * blockDim.x + threadIdx.x;
    const float* src; __half* dst; size_t off;
    if (i < NX4)                { src = X;     dst = g_X16;              off = i; }
    else if (i < NX4 + NW4)     { src = Wih_f; dst = g_Wih16;            off = i - NX4; }
    else if (i < NX4 + 2 * NW4) { src = Wih_b; dst = g_Wih16 + G3n * In; off = i - NX4 - NW4; }
    else if (i < NX4 + 3 * NW4) { src = Whh_f; dst = g_Whh16;            off = i - NX4 - 2 * NW4; }
    else if (i < NX4 + 4 * NW4) { src = Whh_b; dst = g_Whh16 + G3n * Hn; off = i - NX4 - 3 * NW4; }
    else return;
    float4 v = reinterpret_cast<const float4*>(src)[off];
    reinterpret_cast<__half2*>(dst)[2 * off]     = __floats2half2_rn(v.x, v.y);
    reinterpret_cast<__half2*>(dst)[2 * off + 1] = __floats2half2_rn(v.z, v.w);
}

// ---------------------------------------------------------------------------
// Input GEMM (unchanged, proven): GX = X @ Wih^T + biases
// ---------------------------------------------------------------------------
__global__ void __launch_bounds__(NT, 2)
input_gemm(const float* __restrict__ bih_f, const float* __restrict__ bhh_f,
           const float* __restrict__ bih_b, const float* __restrict__ bhh_b)
{
    extern __shared__ __half smh[];
    const uint32_t sm_u32 = (uint32_t)__cvta_generic_to_shared(smh);

    const int tid = threadIdx.x;
    const int warp = tid >> 5, lane = tid & 31;
    const int wm = warp >> 2, wn = warp & 3;
    const int lane8 = lane & 7, laneB = lane >> 3;

    const int c0 = blockIdx.x * 32;
    const size_t m0 = (size_t)blockIdx.y * 128;
    const int dir = blockIdx.z;

    const float* bih = dir ? bih_b : bih_f;
    const float* bhh = dir ? bhh_b : bhh_f;
    const __half* Wt = g_Wih16 + (size_t)dir * G3n * In;

    const int aRow = tid >> 2, aChk = (tid & 3) * 8;
    const __half* srcA0 = g_X16 + (m0 + aRow) * In;
    const __half* srcA1 = g_X16 + (m0 + aRow + 64) * In;
    const int bIdx1 = tid + 256;
    const int bRow0 = tid >> 2, bChk0 = (tid & 3) * 8;
    const int bRow1 = bIdx1 >> 2, bChk1 = (bIdx1 & 3) * 8;
    const __half* srcB0 = Wt + (size_t)((bRow0 >> 5) * Hn + c0 + (bRow0 & 31)) * In;
    const __half* srcB1 = (bIdx1 < 384)
        ? Wt + (size_t)((bRow1 >> 5) * Hn + c0 + (bRow1 & 31)) * In : nullptr;

    int a_off[4], b_off[3];
    #pragma unroll
    for (int mf = 0; mf < 4; mf++)
        a_off[mf] = (wm * 64 + mf * 16 + lane8 + 8 * (laneB & 1)) * ASTH + 8 * (lane >> 4);
    #pragma unroll
    for (int gt = 0; gt < 3; gt++)
        b_off[gt] = (gt * 32 + wn * 8 + lane8) * ASTH + 8 * laneB;

    float acc[3][4][4];
    #pragma unroll
    for (int gt = 0; gt < 3; gt++)
        #pragma unroll
        for (int mi = 0; mi < 4; mi++)
            #pragma unroll
            for (int q = 0; q < 4; q++) acc[gt][mi][q] = 0.f;

    auto issue = [&](int kc_i) {
        const uint32_t base = sm_u32 + (kc_i % 3) * IG_STAGE_B;
        const int kco = kc_i * 32;
        cpasync16(base + (uint32_t)(aRow * ASTH + aChk) * 2, srcA0 + kco + aChk, 16);
        cpasync16(base + (uint32_t)((aRow + 64) * ASTH + aChk) * 2, srcA1 + kco + aChk, 16);
        cpasync16(base + (uint32_t)(IG_BOFF_H + bRow0 * ASTH + bChk0) * 2, srcB0 + kco + bChk0, 16);
        if (srcB1)
            cpasync16(base + (uint32_t)(IG_BOFF_H + bRow1 * ASTH + bChk1) * 2, srcB1 + kco + bChk1, 16);
    };

    issue(0); CP_COMMIT();
    issue(1); CP_COMMIT();

    for (int kc_i = 0; kc_i < 8; kc_i++) {
        CP_WAIT1();
        __syncthreads();
        if (kc_i + 2 < 8) issue(kc_i + 2);
        CP_COMMIT();

        const uint32_t Ab = sm_u32 + (kc_i % 3) * IG_STAGE_B;
        const uint32_t Bb = Ab + IG_BOFF_H * 2;

        uint32_t bfr[3][4];
        #pragma unroll
        for (int gt = 0; gt < 3; gt++) LDSM4(bfr[gt], Bb + b_off[gt] * 2);
        #pragma unroll
        for (int ks = 0; ks < 2; ks++) {
            #pragma unroll
            for (int mf = 0; mf < 4; mf++) {
                uint32_t af[4];
                LDSM4(af, Ab + (a_off[mf] + 16 * ks) * 2);
                #pragma unroll
                for (int gt = 0; gt < 3; gt++)
                    mma16(acc[gt][mf], af, bfr[gt][2 * ks], bfr[gt][2 * ks + 1]);
            }
        }
    }

    __half* GXd = g_GX + (size_t)dir * MI * G3n;
    const int g = lane >> 2, tk = lane & 3;
    const int colb = c0 + wn * 8 + 2 * tk;
    #pragma unroll
    for (int gt = 0; gt < 3; gt++) {
        int gcol = gt * Hn + colb;
        float b0 = bih[gcol]     + (gt < 2 ? bhh[gcol]     : 0.f);
        float b1 = bih[gcol + 1] + (gt < 2 ? bhh[gcol + 1] : 0.f);
        #pragma unroll
        for (int mi = 0; mi < 4; mi++) {
            size_t r0 = m0 + (size_t)(wm * 64 + mi * 16 + g);
            *reinterpret_cast<__half2*>(GXd + r0 * G3n + gcol) =
                __floats2half2_rn(acc[gt][mi][0] + b0, acc[gt][mi][1] + b1);
            *reinterpret_cast<__half2*>(GXd + (r0 + 8) * G3n + gcol) =
                __floats2half2_rn(acc[gt][mi][2] + b0, acc[gt][mi][3] + b1);
        }
    }
}

// ---------------------------------------------------------------------------
static __device__ __forceinline__ float
row_scale(int rg, int j, int dir, const int* __restrict__ D)
{
    int blk = (rg >> 6) & 63, b = rg & 63;
    int t = dir ? (blk * TBn + TBn - 1 - j) : (blk * TBn + j);
    int m = dir ? ((t == SEQn - 1) ? 0 : D[(t + 1) * Bn + b]) : D[t * Bn + b];
    return 1.f - (float)m;
}

static __device__ __forceinline__ const __half*
row_src(int rg, int j, int rnd, int dir, const __half* Sread)
{
    if (j > 0) return Sread + (size_t)rg * Hn;
    if (rnd == 1) {
        int blk = (rg >> 6) & 63;
        int nb = dir ? blk + 1 : blk - 1;
        if (nb >= 0 && nb < NBLKn)
            return g_End16 + (size_t)(rg + (dir ? Bn : -Bn)) * Hn;
    }
    return nullptr;
}

static __device__ __forceinline__ void bar_sync(unsigned* cnt, unsigned* gen, unsigned n)
{
    __threadfence();
    __syncthreads();
    if (threadIdx.x == 0) {
        unsigned gv = *(volatile unsigned*)gen;
        unsigned c = atomicAdd(cnt, 1u);
        if (c == n - 1) {
            atomicExch(cnt, 0u);
            __threadfence();
            atomicAdd(gen, 1u);
        } else {
            while (*(volatile unsigned*)gen == gv) { __nanosleep(32); }
        }
    }
    __syncthreads();
    __threadfence();
}

// ---------------------------------------------------------------------------
// Persistent phase kernel: 64-wide K-chunks (8 syncs/step), GX via early
// register LDGs (commit groups carry only L2-resident state loads).
// ---------------------------------------------------------------------------
__global__ void __launch_bounds__(NT, 2)
phase_persistent(const int* __restrict__ D,
                 const float* __restrict__ bhh_f, const float* __restrict__ bhh_b,
                 float* __restrict__ out)
{
    extern __shared__ __half smh[];
    const uint32_t smA_u = (uint32_t)__cvta_generic_to_shared(smh);
    const uint32_t smB_u = smA_u + PP_B_OFF_H * 2;
    __half* smB = smh + PP_B_OFF_H;

    const int tid = threadIdx.x;
    const int warp = tid >> 5, lane = tid & 31;
    const int wm = warp >> 2, wn = warp & 3;
    const int lane8 = lane & 7, laneB = lane >> 3;

    const int cta = blockIdx.x;
    const int mpair = cta >> 3;
    const int c0 = (cta & 7) * 32;
    const int kch2 = (cta & 7) >> 1;                 // 64-wide chunk containing our cols
    const int m0base = mpair * 256;
    const int dir = m0base >> 12;

    const float* bhh = dir ? bhh_b : bhh_f;

    // resident Whh slice: 96 rows x 256 halfs
    {
        const __half* Wt = g_Whh16 + (size_t)dir * G3n * Hn;
        for (int idx = tid; idx < 96 * 32; idx += NT) {
            int row = idx >> 5, seg = (idx & 31) * 8;
            const float4 v = *reinterpret_cast<const float4*>(
                Wt + (size_t)((row >> 5) * Hn + c0 + (row & 31)) * Hn + seg);
            *reinterpret_cast<float4*>(smB + row * BSTH + seg) = v;
        }
    }
    __syncthreads();

    int a_off[4], b_off[3];
    #pragma unroll
    for (int mf = 0; mf < 4; mf++)
        a_off[mf] = (wm * 64 + mf * 16 + lane8 + 8 * (laneB & 1)) * A2STH + 8 * (lane >> 4);
    #pragma unroll
    for (int gt = 0; gt < 3; gt++)
        b_off[gt] = (gt * 32 + wn * 8 + lane8) * BSTH + 8 * laneB;

    const int g = lane >> 2, tk = lane & 3;
    const int lc = wn * 8 + 2 * tk;
    const int colb = c0 + lc;
    const int hoff = ((cta & 7) & 1) * 32 + lc;      // col offset within chunk kch2
    const float2 bn2 = *reinterpret_cast<const float2*>(bhh + 2 * Hn + colb);

    // cp.async A mapping: thread covers row tid>>1, half (tid&1) of each 128B chunk row
    const int aRow = tid >> 1, aHalf = (tid & 1) * 32;   // halfs
    const __half* GXd = g_GX + (size_t)dir * MI * G3n;

    for (int step = 0; step < 2 * TBn; step++) {
        const int rnd = step >> 5, j = step & 31, cur = step & 1;
        if (step == TBn)  bar_sync(&g_barc, &g_barg, NCTA);
        else if (step)    bar_sync(&g_lbc[mpair], &g_lbg[mpair], 8);

        __half* Swrite16 = g_State16[cur ^ 1];

        const __half* sA[2];
        #pragma unroll
        for (int mt = 0; mt < 2; mt++)
            sA[mt] = row_src(m0base + mt * 128 + aRow, j, rnd, dir, g_State16[cur]);

        __half2 gxv[24];
        auto loadGX = [&](int mt) {
            #pragma unroll
            for (int mi = 0; mi < 4; mi++)
                #pragma unroll
                for (int p = 0; p < 2; p++) {
                    int row = wm * 64 + mi * 16 + g + 8 * p;
                    int rg = m0base + mt * 128 + row;
                    int blk = (rg >> 6) & 63, b = rg & 63;
                    int t = dir ? (blk * TBn + TBn - 1 - j) : (blk * TBn + j);
                    const __half* base = GXd + (size_t)(t * Bn + b) * G3n + colb;
                    gxv[(mi * 2 + p) * 3 + 0] = *reinterpret_cast<const __half2*>(base);
                    gxv[(mi * 2 + p) * 3 + 1] = *reinterpret_cast<const __half2*>(base + Hn);
                    gxv[(mi * 2 + p) * 3 + 2] = *reinterpret_cast<const __half2*>(base + 2 * Hn);
                }
        };

        auto issueA = [&](int c) {   // c in 0..7: mt=c>>2, 64-wide k-chunk = c&3
            const uint32_t base = smA_u + (c % 3) * A2_STAGE_B;
            const int kco = (c & 3) * 64;
            const __half* s = sA[c >> 2];
            const __half* dummy = g_Whh16;
            #pragma unroll
            for (int sgi = 0; sgi < 4; sgi++) {
                uint32_t dst = base + (uint32_t)(aRow * A2STH + aHalf + sgi * 8) * 2;
                cpasync16(dst, s ? s + kco + aHalf + sgi * 8 : dummy, s ? 16 : 0);
            }
        };

        loadGX(0);
        issueA(0); CP_COMMIT();
        issueA(1); CP_COMMIT();

        #pragma unroll 1
        for (int mt = 0; mt < 2; mt++) {
            float acc[3][4][4];
            #pragma unroll
            for (int gt = 0; gt < 3; gt++)
                #pragma unroll
                for (int mi = 0; mi < 4; mi++)
                    #pragma unroll
                    for (int q = 0; q < 4; q++) acc[gt][mi][q] = 0.f;

            __half2 hureg[8];

            #pragma unroll 1
            for (int kc = 0; kc < 4; kc++) {
                const int c = mt * 4 + kc;
                CP_WAIT1();
                __syncthreads();
                if (c + 2 < 8) issueA(c + 2);
                CP_COMMIT();

                const uint32_t Ab = smA_u + (c % 3) * A2_STAGE_B;
                const __half* Ah = smh + (c % 3) * A2_STAGE_H;

                if (kc == kch2) {
                    #pragma unroll
                    for (int q = 0; q < 8; q++) {
                        int row = wm * 64 + (q >> 1) * 16 + g + 8 * (q & 1);
                        hureg[q] = *reinterpret_cast<const __half2*>(Ah + row * A2STH + hoff);
                    }
                }

                // B fragments: two 32-k halves of this 64-k chunk
                uint32_t bfr[3][2][4];
                #pragma unroll
                for (int gt = 0; gt < 3; gt++) {
                    LDSM4(bfr[gt][0], smB_u + (uint32_t)(kc * 64 + b_off[gt]) * 2);
                    LDSM4(bfr[gt][1], smB_u + (uint32_t)(kc * 64 + 32 + b_off[gt]) * 2);
                }
                #pragma unroll
                for (int ks = 0; ks < 4; ks++) {
                    #pragma unroll
                    for (int mf = 0; mf < 4; mf++) {
                        uint32_t af[4];
                        LDSM4(af, Ab + (a_off[mf] + 16 * ks) * 2);
                        #pragma unroll
                        for (int gt = 0; gt < 3; gt++)
                            mma16(acc[gt][mf], af,
                                  bfr[gt][ks >> 1][2 * (ks & 1)],
                                  bfr[gt][ks >> 1][2 * (ks & 1) + 1]);
                    }
                }
            }

            // ---- epilogue (GX from regs, hu from regs) ----
            const int m0 = m0base + mt * 128;
            #pragma unroll
            for (int mi = 0; mi < 4; mi++) {
                #pragma unroll
                for (int p = 0; p < 2; p++) {
                    int row = wm * 64 + mi * 16 + g + 8 * p;
                    int rg = m0 + row;
                    int blk = (rg >> 6) & 63, b = rg & 63;
                    int t = dir ? (blk * TBn + TBn - 1 - j) : (blk * TBn + j);
                    int tb = t * Bn + b;

                    float2 hu = __half22float2(hureg[mi * 2 + p]);
                    float2 gr = __half22float2(gxv[(mi * 2 + p) * 3 + 0]);
                    float2 gz = __half22float2(gxv[(mi * 2 + p) * 3 + 1]);
                    float2 gn = __half22float2(gxv[(mi * 2 + p) * 3 + 2]);

                    float rv0 = 1.f / (1.f + __expf(-(gr.x + acc[0][mi][2 * p])));
                    float rv1 = 1.f / (1.f + __expf(-(gr.y + acc[0][mi][2 * p + 1])));
                    float zv0 = 1.f / (1.f + __expf(-(gz.x + acc[1][mi][2 * p])));
                    float zv1 = 1.f / (1.f + __expf(-(gz.y + acc[1][mi][2 * p + 1])));
                    float nv0 = tanhf(gn.x + rv0 * (acc[2][mi][2 * p] + bn2.x));
                    float nv1 = tanhf(gn.y + rv1 * (acc[2][mi][2 * p + 1] + bn2.y));
                    float h0 = (1.f - zv0) * nv0 + zv0 * hu.x;
                    float h1 = (1.f - zv1) * nv1 + zv1 * hu.y;

                    if (j < TBn - 1) {
                        float wsc = row_scale(rg, j + 1, dir, D);
                        *reinterpret_cast<__half2*>(Swrite16 + (size_t)rg * Hn + colb) =
                            __floats2half2_rn(h0 * wsc, h1 * wsc);
                    } else if (rnd == 0) {
                        int rgc = rg + (dir ? -Bn : Bn);
                        bool valid = dir ? (blk > 0) : (blk < NBLKn - 1);
                        float wsc = valid ? row_scale(rgc, 0, dir, D) : 0.f;
                        *reinterpret_cast<__half2*>(g_End16 + (size_t)rg * Hn + colb) =
                            __floats2half2_rn(h0 * wsc, h1 * wsc);
                    }
                    if (rnd == 1)
                        *reinterpret_cast<float2*>(out + (size_t)tb * (2 * Hn) + dir * Hn + colb) =
                            make_float2(h0, h1);
                }
            }
            if (mt == 0) loadGX(1);   // prefetch m-tile 1 epilogue operands
        }
    }
}

// ---------------------------------------------------------------------------
extern "C" void kernel_launch(void* const* d_in, const int* in_sizes, int n_in,
                              void* d_out, int out_size)
{
    const float* X     = (const float*)d_in[0];
    const int*   D     = (const int*)d_in[1];
    const float* Wih_f = (const float*)d_in[2];
    const float* Whh_f = (const float*)d_in[3];
    const float* bih_f = (const float*)d_in[4];
    const float* bhh_f = (const float*)d_in[5];
    const float* Wih_b = (const float*)d_in[6];
    const float* Whh_b = (const float*)d_in[7];
    const float* bih_b = (const float*)d_in[8];
    const float* bhh_b = (const float*)d_in[9];
    float* out = (float*)d_out;

    cudaFuncSetAttribute(input_gemm, cudaFuncAttributeMaxDynamicSharedMemorySize, IG_SMEM);
    cudaFuncSetAttribute(phase_persistent, cudaFuncAttributeMaxDynamicSharedMemorySize, PP_SMEM);

    const size_t ntot = NX4 + 4 * NW4;
    convert_all<<<(unsigned)((ntot + 255) / 256), 256>>>(X, Wih_f, Wih_b, Whh_f, Whh_b);

    input_gemm<<<dim3(Hn / 32, MI / 128, 2), NT, IG_SMEM>>>(bih_f, bhh_f, bih_b, bhh_b);

    phase_persistent<<<NCTA, NT, PP_SMEM>>>(D, bhh_f, bhh_b, out);
}

// round 11
// speedup vs baseline: 1.1580x; 1.1580x over previous
#include <cuda_runtime.h>
#include <cuda_fp16.h>
#include <cstdint>
#include <cstddef>

#define SEQn 2048
#define Bn   64
#define In   256
#define Hn   256
#define G3n  768
#define TBn  32
#define NBLKn 64
#define MR   8192      // 2 dirs * 64 blocks * 64 batch
#define MI   131072    // SEQ*B

#define NT   256       // 8 warps: 2(m) x 4(n)
#define ASTH 40        // A row stride (halfs)
#define BSTH 264       // resident-B row stride (halfs, conflict-free)
#define GXSTH 104      // GX smem row stride (halfs, conflict-free)
#define A_STAGE_H (128 * ASTH)
#define NCTA 256
#define NMP  32
#define MT_PER_CTA 16  // input_gemm m-tiles per CTA

// input_gemm smem: 3 A stages + resident B
#define IG_B_OFF_H (3 * A_STAGE_H)
#define IG_SMEM ((IG_B_OFF_H + 96 * BSTH) * 2)      // 81408 B

// phase smem: 3 A stages + resident B + GX buffer (R9 layout)
#define PP_B_OFF_H  (3 * A_STAGE_H)
#define PP_GX_OFF_H (PP_B_OFF_H + 96 * BSTH)
#define PP_SMEM ((PP_GX_OFF_H + 128 * GXSTH) * 2)   // 108032 B

__device__ __half g_GX[(size_t)2 * MI * G3n];
__device__ __half g_X16[(size_t)MI * In];
__device__ __half g_Wih16[(size_t)2 * G3n * In];
__device__ __half g_Whh16[(size_t)2 * G3n * Hn];
__device__ __half g_State16[2][(size_t)MR * Hn];
__device__ __half g_End16[(size_t)MR * Hn];
__device__ unsigned g_barc;
__device__ unsigned g_barg;
__device__ unsigned g_lbc[NMP];
__device__ unsigned g_lbg[NMP];

static __device__ __forceinline__ void mma16(float c[4], const uint32_t a[4],
                                             uint32_t b0, uint32_t b1) {
    asm volatile(
        "mma.sync.aligned.m16n8k16.row.col.f32.f16.f16.f32 "
        "{%0,%1,%2,%3}, {%4,%5,%6,%7}, {%8,%9}, {%0,%1,%2,%3};\n"
        : "+f"(c[0]), "+f"(c[1]), "+f"(c[2]), "+f"(c[3])
        : "r"(a[0]), "r"(a[1]), "r"(a[2]), "r"(a[3]), "r"(b0), "r"(b1));
}

#define LDSM4(r, addr) \
    asm volatile("ldmatrix.sync.aligned.m8n8.x4.shared.b16 {%0,%1,%2,%3}, [%4];" \
                 : "=r"((r)[0]), "=r"((r)[1]), "=r"((r)[2]), "=r"((r)[3]) : "r"(addr))

static __device__ __forceinline__ void cpasync16(uint32_t dst, const void* src, int srcsize) {
    asm volatile("cp.async.cg.shared.global [%0], [%1], 16, %2;\n"
                 :: "r"(dst), "l"(src), "r"(srcsize));
}
#define CP_COMMIT() asm volatile("cp.async.commit_group;\n" ::: "memory")
#define CP_WAIT1()  asm volatile("cp.async.wait_group 1;\n" ::: "memory")

// ---------------------------------------------------------------------------
#define NX4 ((size_t)MI * In / 4)
#define NW4 ((size_t)G3n * In / 4)

__global__ void convert_all(const float* __restrict__ X,
                            const float* __restrict__ Wih_f, const float* __restrict__ Wih_b,
                            const float* __restrict__ Whh_f, const float* __restrict__ Whh_b)
{
    size_t i = (size_t)blockIdx.x * blockDim.x + threadIdx.x;
    const float* src; __half* dst; size_t off;
    if (i < NX4)                { src = X;     dst = g_X16;              off = i; }
    else if (i < NX4 + NW4)     { src = Wih_f; dst = g_Wih16;            off = i - NX4; }
    else if (i < NX4 + 2 * NW4) { src = Wih_b; dst = g_Wih16 + G3n * In; off = i - NX4 - NW4; }
    else if (i < NX4 + 3 * NW4) { src = Whh_f; dst = g_Whh16;            off = i - NX4 - 2 * NW4; }
    else if (i < NX4 + 4 * NW4) { src = Whh_b; dst = g_Whh16 + G3n * Hn; off = i - NX4 - 3 * NW4; }
    else return;
    float4 v = reinterpret_cast<const float4*>(src)[off];
    reinterpret_cast<__half2*>(dst)[2 * off]     = __floats2half2_rn(v.x, v.y);
    reinterpret_cast<__half2*>(dst)[2 * off + 1] = __floats2half2_rn(v.z, v.w);
}

// ---------------------------------------------------------------------------
// Input GEMM v2: resident Wih slice + 16 streamed m-tiles per CTA.
// grid (8 colgroups fastest, 64 m-CTAs, 2 dirs) = 1024 CTAs.
// ---------------------------------------------------------------------------
__global__ void __launch_bounds__(NT, 2)
input_gemm(const float* __restrict__ bih_f, const float* __restrict__ bhh_f,
           const float* __restrict__ bih_b, const float* __restrict__ bhh_b)
{
    extern __shared__ __half smh[];
    const uint32_t smA_u = (uint32_t)__cvta_generic_to_shared(smh);
    const uint32_t smB_u = smA_u + IG_B_OFF_H * 2;
    __half* smB = smh + IG_B_OFF_H;

    const int tid = threadIdx.x;
    const int warp = tid >> 5, lane = tid & 31;
    const int wm = warp >> 2, wn = warp & 3;
    const int lane8 = lane & 7, laneB = lane >> 3;

    const int c0 = blockIdx.x * 32;
    const size_t mbase = (size_t)blockIdx.y * (MT_PER_CTA * 128);
    const int dir = blockIdx.z;

    const float* bih = dir ? bih_b : bih_f;
    const float* bhh = dir ? bhh_b : bhh_f;

    // resident Wih slice: 96 rows x 256 halfs
    {
        const __half* Wt = g_Wih16 + (size_t)dir * G3n * In;
        for (int idx = tid; idx < 96 * 32; idx += NT) {
            int row = idx >> 5, seg = (idx & 31) * 8;
            const float4 v = *reinterpret_cast<const float4*>(
                Wt + (size_t)((row >> 5) * Hn + c0 + (row & 31)) * In + seg);
            *reinterpret_cast<float4*>(smB + row * BSTH + seg) = v;
        }
    }
    __syncthreads();

    int a_off[4], b_off[3];
    #pragma unroll
    for (int mf = 0; mf < 4; mf++)
        a_off[mf] = (wm * 64 + mf * 16 + lane8 + 8 * (laneB & 1)) * ASTH + 8 * (lane >> 4);
    #pragma unroll
    for (int gt = 0; gt < 3; gt++)
        b_off[gt] = (gt * 32 + wn * 8 + lane8) * BSTH + 8 * laneB;

    const int aRow = tid >> 2, aChk = (tid & 3) * 8;   // 64 rows x 4 pieces per cpasync pass
    const int g = lane >> 2, tk = lane & 3;
    const int colb = c0 + wn * 8 + 2 * tk;

    float bias[3][2];
    #pragma unroll
    for (int gt = 0; gt < 3; gt++) {
        int gcol = gt * Hn + colb;
        bias[gt][0] = bih[gcol]     + (gt < 2 ? bhh[gcol]     : 0.f);
        bias[gt][1] = bih[gcol + 1] + (gt < 2 ? bhh[gcol + 1] : 0.f);
    }

    __half* GXd = g_GX + (size_t)dir * MI * G3n;

    auto issueA = [&](int c) {   // global chunk stream: tile = c>>3, k-chunk = c&7
        const uint32_t base = smA_u + (c % 3) * (A_STAGE_H * 2);
        const int kco = (c & 7) * 32;
        const __half* s = g_X16 + (mbase + (size_t)(c >> 3) * 128 + aRow) * In + kco + aChk;
        cpasync16(base + (uint32_t)(aRow * ASTH + aChk) * 2, s, 16);
        cpasync16(base + (uint32_t)((aRow + 64) * ASTH + aChk) * 2, s + (size_t)64 * In, 16);
    };

    issueA(0); CP_COMMIT();
    issueA(1); CP_COMMIT();

    const int NCHUNK = MT_PER_CTA * 8;
    #pragma unroll 1
    for (int mt = 0; mt < MT_PER_CTA; mt++) {
        float acc[3][4][4];
        #pragma unroll
        for (int gt = 0; gt < 3; gt++)
            #pragma unroll
            for (int mi = 0; mi < 4; mi++)
                #pragma unroll
                for (int q = 0; q < 4; q++) acc[gt][mi][q] = 0.f;

        #pragma unroll 1
        for (int kc = 0; kc < 8; kc++) {
            const int c = mt * 8 + kc;
            CP_WAIT1();
            __syncthreads();
            if (c + 2 < NCHUNK) issueA(c + 2);
            CP_COMMIT();

            const uint32_t Ab = smA_u + (c % 3) * (A_STAGE_H * 2);

            uint32_t bfr[3][4];
            #pragma unroll
            for (int gt = 0; gt < 3; gt++)
                LDSM4(bfr[gt], smB_u + (uint32_t)(kc * 32 + b_off[gt]) * 2);
            #pragma unroll
            for (int ks = 0; ks < 2; ks++) {
                #pragma unroll
                for (int mf = 0; mf < 4; mf++) {
                    uint32_t af[4];
                    LDSM4(af, Ab + (a_off[mf] + 16 * ks) * 2);
                    #pragma unroll
                    for (int gt = 0; gt < 3; gt++)
                        mma16(acc[gt][mf], af, bfr[gt][2 * ks], bfr[gt][2 * ks + 1]);
                }
            }
        }

        // epilogue: biases + fp16 GX store
        const size_t m0 = mbase + (size_t)mt * 128;
        #pragma unroll
        for (int gt = 0; gt < 3; gt++) {
            int gcol = gt * Hn + colb;
            #pragma unroll
            for (int mi = 0; mi < 4; mi++) {
                size_t r0 = m0 + (size_t)(wm * 64 + mi * 16 + g);
                *reinterpret_cast<__half2*>(GXd + r0 * G3n + gcol) =
                    __floats2half2_rn(acc[gt][mi][0] + bias[gt][0], acc[gt][mi][1] + bias[gt][1]);
                *reinterpret_cast<__half2*>(GXd + (r0 + 8) * G3n + gcol) =
                    __floats2half2_rn(acc[gt][mi][2] + bias[gt][0], acc[gt][mi][3] + bias[gt][1]);
            }
        }
    }
}

// ---------------------------------------------------------------------------
static __device__ __forceinline__ float
row_scale(int rg, int j, int dir, const int* __restrict__ D)
{
    int blk = (rg >> 6) & 63, b = rg & 63;
    int t = dir ? (blk * TBn + TBn - 1 - j) : (blk * TBn + j);
    int m = dir ? ((t == SEQn - 1) ? 0 : D[(t + 1) * Bn + b]) : D[t * Bn + b];
    return 1.f - (float)m;
}

static __device__ __forceinline__ const __half*
row_src(int rg, int j, int rnd, int dir, const __half* Sread)
{
    if (j > 0) return Sread + (size_t)rg * Hn;
    if (rnd == 1) {
        int blk = (rg >> 6) & 63;
        int nb = dir ? blk + 1 : blk - 1;
        if (nb >= 0 && nb < NBLKn)
            return g_End16 + (size_t)(rg + (dir ? Bn : -Bn)) * Hn;
    }
    return nullptr;
}

static __device__ __forceinline__ void bar_sync(unsigned* cnt, unsigned* gen, unsigned n)
{
    __threadfence();
    __syncthreads();
    if (threadIdx.x == 0) {
        unsigned gv = *(volatile unsigned*)gen;
        unsigned c = atomicAdd(cnt, 1u);
        if (c == n - 1) {
            atomicExch(cnt, 0u);
            __threadfence();
            atomicAdd(gen, 1u);
        } else {
            while (*(volatile unsigned*)gen == gv) { __nanosleep(32); }
        }
    }
    __syncthreads();
    __threadfence();
}

// ---------------------------------------------------------------------------
// Persistent phase kernel — exact R9 version (best known: 1941 us total).
// ---------------------------------------------------------------------------
__global__ void __launch_bounds__(NT, 2)
phase_persistent(const int* __restrict__ D,
                 const float* __restrict__ bhh_f, const float* __restrict__ bhh_b,
                 float* __restrict__ out)
{
    extern __shared__ __half smh[];
    const uint32_t smA_u = (uint32_t)__cvta_generic_to_shared(smh);
    const uint32_t smB_u = smA_u + PP_B_OFF_H * 2;
    const uint32_t smGX_u = smA_u + PP_GX_OFF_H * 2;
    __half* smB  = smh + PP_B_OFF_H;
    __half* smGX = smh + PP_GX_OFF_H;

    const int tid = threadIdx.x;
    const int warp = tid >> 5, lane = tid & 31;
    const int wm = warp >> 2, wn = warp & 3;
    const int lane8 = lane & 7, laneB = lane >> 3;

    const int cta = blockIdx.x;
    const int mpair = cta >> 3;
    const int c0 = (cta & 7) * 32;
    const int kch = cta & 7;
    const int m0base = mpair * 256;
    const int dir = m0base >> 12;

    const float* bhh = dir ? bhh_b : bhh_f;

    {
        const __half* Wt = g_Whh16 + (size_t)dir * G3n * Hn;
        for (int idx = tid; idx < 96 * 32; idx += NT) {
            int row = idx >> 5, seg = (idx & 31) * 8;
            const float4 v = *reinterpret_cast<const float4*>(
                Wt + (size_t)((row >> 5) * Hn + c0 + (row & 31)) * Hn + seg);
            *reinterpret_cast<float4*>(smB + row * BSTH + seg) = v;
        }
    }
    __syncthreads();

    int a_off[4], b_off[3];
    #pragma unroll
    for (int mf = 0; mf < 4; mf++)
        a_off[mf] = (wm * 64 + mf * 16 + lane8 + 8 * (laneB & 1)) * ASTH + 8 * (lane >> 4);
    #pragma unroll
    for (int gt = 0; gt < 3; gt++)
        b_off[gt] = (gt * 32 + wn * 8 + lane8) * BSTH + 8 * laneB;

    const int aRow = tid >> 2, aChk = (tid & 3) * 8;
    const int g = lane >> 2, tk = lane & 3;
    const int lc = wn * 8 + 2 * tk;
    const int colb = c0 + lc;
    const float2 bn2 = *reinterpret_cast<const float2*>(bhh + 2 * Hn + colb);

    const int gxrow = tid & 127;
    const int gxp0 = tid >> 7;
    const __half* GXd = g_GX + (size_t)dir * MI * G3n;

    for (int step = 0; step < 2 * TBn; step++) {
        const int rnd = step >> 5, j = step & 31, cur = step & 1;
        if (step == TBn)  bar_sync(&g_barc, &g_barg, NCTA);
        else if (step)    bar_sync(&g_lbc[mpair], &g_lbg[mpair], 8);

        __half* Swrite16 = g_State16[cur ^ 1];

        const __half* sA[2][2];
        const __half* gxsrc[2];
        #pragma unroll
        for (int mt = 0; mt < 2; mt++) {
            sA[mt][0] = row_src(m0base + mt * 128 + aRow,      j, rnd, dir, g_State16[cur]);
            sA[mt][1] = row_src(m0base + mt * 128 + aRow + 64, j, rnd, dir, g_State16[cur]);
            int rg = m0base + mt * 128 + gxrow;
            int blk = (rg >> 6) & 63, b = rg & 63;
            int t = dir ? (blk * TBn + TBn - 1 - j) : (blk * TBn + j);
            gxsrc[mt] = GXd + (size_t)(t * Bn + b) * G3n;
        }

        auto issueA = [&](int c) {
            const uint32_t base = smA_u + (c % 3) * (A_STAGE_H * 2);
            const int kco = (c & 7) * 32;
            const __half* s0 = sA[c >> 3][0];
            const __half* s1 = sA[c >> 3][1];
            const __half* dummy = g_Whh16;
            cpasync16(base + (uint32_t)(aRow * ASTH + aChk) * 2,
                      s0 ? s0 + kco + aChk : dummy, s0 ? 16 : 0);
            cpasync16(base + (uint32_t)((aRow + 64) * ASTH + aChk) * 2,
                      s1 ? s1 + kco + aChk : dummy, s1 ? 16 : 0);
        };
        auto issueGX = [&](int mt, int s) {
            int p = gxp0 + 2 * s;
            cpasync16(smGX_u + (uint32_t)(gxrow * GXSTH + p * 8) * 2,
                      gxsrc[mt] + (p >> 2) * Hn + c0 + (p & 3) * 8, 16);
        };

        issueA(0); issueGX(0, 0); CP_COMMIT();
        issueA(1); issueGX(0, 1); CP_COMMIT();

        #pragma unroll 1
        for (int mt = 0; mt < 2; mt++) {
            float acc[3][4][4];
            #pragma unroll
            for (int gt = 0; gt < 3; gt++)
                #pragma unroll
                for (int mi = 0; mi < 4; mi++)
                    #pragma unroll
                    for (int q = 0; q < 4; q++) acc[gt][mi][q] = 0.f;

            __half2 hureg[8];

            #pragma unroll 1
            for (int kc = 0; kc < 8; kc++) {
                const int c = mt * 8 + kc;
                CP_WAIT1();
                __syncthreads();
                if (c + 2 < 16) issueA(c + 2);
                if (c < 4) issueGX(0, c + 2);
                else if (c >= 8 && c < 14) issueGX(1, c - 8);
                CP_COMMIT();

                const uint32_t Ab = smA_u + (c % 3) * (A_STAGE_H * 2);
                const __half* Ah = smh + (c % 3) * A_STAGE_H;
                const uint32_t Bk = smB_u + (uint32_t)(kc * 32) * 2;

                if (kc == kch) {
                    #pragma unroll
                    for (int q = 0; q < 8; q++) {
                        int row = wm * 64 + (q >> 1) * 16 + g + 8 * (q & 1);
                        hureg[q] = *reinterpret_cast<const __half2*>(Ah + row * ASTH + lc);
                    }
                }

                uint32_t bfr[3][4];
                #pragma unroll
                for (int gt = 0; gt < 3; gt++) LDSM4(bfr[gt], Bk + b_off[gt] * 2);
                #pragma unroll
                for (int ks = 0; ks < 2; ks++) {
                    #pragma unroll
                    for (int mf = 0; mf < 4; mf++) {
                        uint32_t af[4];
                        LDSM4(af, Ab + (a_off[mf] + 16 * ks) * 2);
                        #pragma unroll
                        for (int gt = 0; gt < 3; gt++)
                            mma16(acc[gt][mf], af, bfr[gt][2 * ks], bfr[gt][2 * ks + 1]);
                    }
                }
            }

            const int m0 = m0base + mt * 128;
            #pragma unroll
            for (int mi = 0; mi < 4; mi++) {
                #pragma unroll
                for (int p = 0; p < 2; p++) {
                    int row = wm * 64 + mi * 16 + g + 8 * p;
                    int rg = m0 + row;
                    int blk = (rg >> 6) & 63, b = rg & 63;
                    int t = dir ? (blk * TBn + TBn - 1 - j) : (blk * TBn + j);
                    int tb = t * Bn + b;

                    float2 hu = __half22float2(hureg[mi * 2 + p]);

                    const __half* gxs = smGX + row * GXSTH;
                    float2 gr = __half22float2(*reinterpret_cast<const __half2*>(gxs + lc));
                    float2 gz = __half22float2(*reinterpret_cast<const __half2*>(gxs + 32 + lc));
                    float2 gn = __half22float2(*reinterpret_cast<const __half2*>(gxs + 64 + lc));

                    float rv0 = 1.f / (1.f + __expf(-(gr.x + acc[0][mi][2 * p])));
                    float rv1 = 1.f / (1.f + __expf(-(gr.y + acc[0][mi][2 * p + 1])));
                    float zv0 = 1.f / (1.f + __expf(-(gz.x + acc[1][mi][2 * p])));
                    float zv1 = 1.f / (1.f + __expf(-(gz.y + acc[1][mi][2 * p + 1])));
                    float nv0 = tanhf(gn.x + rv0 * (acc[2][mi][2 * p] + bn2.x));
                    float nv1 = tanhf(gn.y + rv1 * (acc[2][mi][2 * p + 1] + bn2.y));
                    float h0 = (1.f - zv0) * nv0 + zv0 * hu.x;
                    float h1 = (1.f - zv1) * nv1 + zv1 * hu.y;

                    if (j < TBn - 1) {
                        float wsc = row_scale(rg, j + 1, dir, D);
                        *reinterpret_cast<__half2*>(Swrite16 + (size_t)rg * Hn + colb) =
                            __floats2half2_rn(h0 * wsc, h1 * wsc);
                    } else if (rnd == 0) {
                        int rgc = rg + (dir ? -Bn : Bn);
                        bool valid = dir ? (blk > 0) : (blk < NBLKn - 1);
                        float wsc = valid ? row_scale(rgc, 0, dir, D) : 0.f;
                        *reinterpret_cast<__half2*>(g_End16 + (size_t)rg * Hn + colb) =
                            __floats2half2_rn(h0 * wsc, h1 * wsc);
                    }
                    if (rnd == 1)
                        *reinterpret_cast<float2*>(out + (size_t)tb * (2 * Hn) + dir * Hn + colb) =
                            make_float2(h0, h1);
                }
            }
        }
    }
}

// ---------------------------------------------------------------------------
extern "C" void kernel_launch(void* const* d_in, const int* in_sizes, int n_in,
                              void* d_out, int out_size)
{
    const float* X     = (const float*)d_in[0];
    const int*   D     = (const int*)d_in[1];
    const float* Wih_f = (const float*)d_in[2];
    const float* Whh_f = (const float*)d_in[3];
    const float* bih_f = (const float*)d_in[4];
    const float* bhh_f = (const float*)d_in[5];
    const float* Wih_b = (const float*)d_in[6];
    const float* Whh_b = (const float*)d_in[7];
    const float* bih_b = (const float*)d_in[8];
    const float* bhh_b = (const float*)d_in[9];
    float* out = (float*)d_out;

    cudaFuncSetAttribute(input_gemm, cudaFuncAttributeMaxDynamicSharedMemorySize, IG_SMEM);
    cudaFuncSetAttribute(phase_persistent, cudaFuncAttributeMaxDynamicSharedMemorySize, PP_SMEM);

    const size_t ntot = NX4 + 4 * NW4;
    convert_all<<<(unsigned)((ntot + 255) / 256), 256>>>(X, Wih_f, Wih_b, Whh_f, Whh_b);

    input_gemm<<<dim3(Hn / 32, MI / (MT_PER_CTA * 128), 2), NT, IG_SMEM>>>(
        bih_f, bhh_f, bih_b, bhh_b);

    phase_persistent<<<NCTA, NT, PP_SMEM>>>(D, bhh_f, bhh_b, out);
}